// round 14
// baseline (speedup 1.0000x reference)
#include <cuda_runtime.h>
#include <cuda_fp16.h>
#include <cstdint>

// GPTQ 4-bit linear, v14: v13's 64x64 warp tile at half-CTA granularity ->
// 2 CTAs/SM (cross-CTA filling of stage-boundary bubbles, now that the
// LDSM crossbar is unsaturated: L1 46% in v13).
//   GEMM: BM=128, BN=128, 4 warps (2Mx2N, warp 64x64), 128 threads,
//         STAGES=3, 97KB smem, tid0 producer, peeled ks3 early empty-arrive.

#define KDIM 4096
#define NDIM 4096
#define MMAX 8192
#define BM 128
#define BN 128
#define BK 64
#define STAGES 3
#define NTHREADS 128
#define KTILES (KDIM / BK)              // 64
#define A_TILE_BYTES (BM * BK * 2)      // 16384
#define B_TILE_BYTES (BN * BK * 2)      // 16384
#define STAGE_BYTES (A_TILE_BYTES + B_TILE_BYTES)     // 32768
#define SMEM_HDR 1024
#define SMEM_TOTAL (SMEM_HDR + STAGES * STAGE_BYTES)  // 99328 -> 2 CTAs/SM

#define XBLKS 16384
#define WBLKS 8192

__device__ __align__(1024) __half g_xh[(size_t)MMAX * KDIM];
__device__ __align__(1024) __half g_wf[(size_t)NDIM * KDIM];

__device__ __forceinline__ uint32_t swz128(uint32_t off) {
    return off ^ ((off >> 3) & 0x70);
}
__device__ __forceinline__ uint32_t smem_u32(const void* p) {
    uint32_t a;
    asm("{ .reg .u64 t; cvta.to.shared.u64 t, %1; cvt.u32.u64 %0, t; }" : "=r"(a) : "l"(p));
    return a;
}
__device__ __forceinline__ void mbar_init(uint32_t mbar, uint32_t count) {
    asm volatile("mbarrier.init.shared.b64 [%0], %1;" :: "r"(mbar), "r"(count) : "memory");
}
__device__ __forceinline__ void mbar_expect_tx(uint32_t mbar, uint32_t bytes) {
    asm volatile("mbarrier.arrive.expect_tx.shared.b64 _, [%0], %1;" :: "r"(mbar), "r"(bytes) : "memory");
}
__device__ __forceinline__ void mbar_arrive(uint32_t mbar) {
    asm volatile("mbarrier.arrive.shared.b64 _, [%0];" :: "r"(mbar) : "memory");
}
__device__ __forceinline__ void mbar_wait(uint32_t mbar, uint32_t parity) {
    asm volatile(
        "{\n\t.reg .pred P;\n\t"
        "WAIT_%=:\n\t"
        "mbarrier.try_wait.parity.acquire.cta.shared::cta.b64 P, [%0], %1, 0x989680;\n\t"
        "@!P bra WAIT_%=;\n\t}"
        :: "r"(mbar), "r"(parity) : "memory");
}
__device__ __forceinline__ void bulk_g2s(uint32_t dst, const void* src, uint32_t bytes, uint32_t mbar) {
    asm volatile(
        "cp.async.bulk.shared::cluster.global.mbarrier::complete_tx::bytes [%0], [%1], %2, [%3];"
        :: "r"(dst), "l"(src), "r"(bytes), "r"(mbar) : "memory");
}
__device__ __forceinline__ void ldsm_x4(uint32_t* r, uint32_t addr) {
    asm volatile("ldmatrix.sync.aligned.m8n8.x4.shared.b16 {%0,%1,%2,%3}, [%4];"
                 : "=r"(r[0]), "=r"(r[1]), "=r"(r[2]), "=r"(r[3]) : "r"(addr));
}
__device__ __forceinline__ void mma_16816(float* c, const uint32_t* a, uint32_t b0, uint32_t b1) {
    asm volatile(
        "mma.sync.aligned.m16n8k16.row.col.f32.f16.f16.f32 "
        "{%0,%1,%2,%3}, {%4,%5,%6,%7}, {%8,%9}, {%0,%1,%2,%3};"
        : "+f"(c[0]), "+f"(c[1]), "+f"(c[2]), "+f"(c[3])
        : "r"(a[0]), "r"(a[1]), "r"(a[2]), "r"(a[3]), "r"(b0), "r"(b1));
}

// ---------------------------------------------------------------------------
// Fused prep: blocks [0, XBLKS) convert x (128-row tiles);
// blocks [XBLKS, XBLKS+WBLKS) build W (128-row tiles).
// ---------------------------------------------------------------------------
__global__ void prep(const float* __restrict__ x,
                     const int* __restrict__ qw, const int* __restrict__ qz,
                     const float* __restrict__ sc) {
    if (blockIdx.x < XBLKS) {
        size_t idx = (size_t)blockIdx.x * blockDim.x + threadIdx.x;  // per 8 elems
        int m  = (int)(idx >> 9);
        int k0 = ((int)idx & 511) << 3;

        const float* src = x + (size_t)m * KDIM + k0;
        float4 v0 = *reinterpret_cast<const float4*>(src);
        float4 v1 = *reinterpret_cast<const float4*>(src + 4);

        union { __half h[8]; uint4 u; } d;
        d.h[0] = __float2half_rn(v0.x); d.h[1] = __float2half_rn(v0.y);
        d.h[2] = __float2half_rn(v0.z); d.h[3] = __float2half_rn(v0.w);
        d.h[4] = __float2half_rn(v1.x); d.h[5] = __float2half_rn(v1.y);
        d.h[6] = __float2half_rn(v1.z); d.h[7] = __float2half_rn(v1.w);

        size_t off = ((size_t)(m >> 7) * KTILES + (k0 >> 6)) * A_TILE_BYTES
                   + swz128((uint32_t)((m & 127) * 128 + (k0 & 63) * 2));
        *reinterpret_cast<uint4*>(reinterpret_cast<char*>(g_xh) + off) = d.u;
    } else {
        int idx = (blockIdx.x - XBLKS) * blockDim.x + threadIdx.x;  // per qw word
        int kw = idx >> 12;                 // k/8: 0..511
        int n  = idx & 4095;
        int g  = kw >> 4;                   // k/128
        float s = sc[g * NDIM + n];
        int z = ((qz[g * (NDIM / 8) + (n >> 3)] >> ((n & 7) * 4)) & 15) + 1;
        int w = qw[kw * NDIM + n];

        union { __half h[8]; uint4 u; } d;
        #pragma unroll
        for (int j = 0; j < 8; j++) {
            int q = (w >> (j * 4)) & 15;
            d.h[j] = __float2half_rn(s * (float)(q - z));
        }

        int k0 = kw << 3;
        size_t off = ((size_t)(n >> 7) * KTILES + (k0 >> 6)) * B_TILE_BYTES
                   + swz128((uint32_t)((n & 127) * 128 + (k0 & 63) * 2));
        *reinterpret_cast<uint4*>(reinterpret_cast<char*>(g_wf) + off) = d.u;
    }
}

// ---------------------------------------------------------------------------
// GEMM: pure fp16, 4 warps (warp tile 64x64), tid0 producer, 2 CTAs/SM
// ---------------------------------------------------------------------------
__global__ __launch_bounds__(NTHREADS, 2)
void gemm_mma(const float* __restrict__ bias, float* __restrict__ out) {
    extern __shared__ char smem[];
    const uint32_t sb = smem_u32(smem);
    const int tid = threadIdx.x;

    const uint32_t mbar0 = sb;   // full[s]=sb+s*16, empty[s]=sb+s*16+8

    if (tid == 0) {
        #pragma unroll
        for (int s = 0; s < STAGES; s++) {
            mbar_init(mbar0 + s * 16, 1);       // full: tx-based
            mbar_init(mbar0 + s * 16 + 8, 4);   // empty: one arrive per warp
        }
    }
    __syncthreads();

    const int bm = blockIdx.y * BM;
    const int bn = blockIdx.x * BN;
    const size_t a_base = (size_t)blockIdx.y * KTILES * A_TILE_BYTES;
    const size_t b_base = (size_t)blockIdx.x * KTILES * B_TILE_BYTES;

    if (tid == 0) {
        #pragma unroll
        for (int s = 0; s < STAGES; s++) {      // prologue: k-tiles 0..2
            uint32_t full = mbar0 + s * 16;
            uint32_t st_s = sb + SMEM_HDR + s * STAGE_BYTES;
            mbar_expect_tx(full, STAGE_BYTES);
            bulk_g2s(st_s, (const char*)g_xh + a_base + (size_t)s * A_TILE_BYTES,
                     A_TILE_BYTES, full);
            bulk_g2s(st_s + A_TILE_BYTES,
                     (const char*)g_wf + b_base + (size_t)s * B_TILE_BYTES,
                     B_TILE_BYTES, full);
        }
    }

    const int warp = tid >> 5, lane = tid & 31;
    const int m0 = (warp >> 1) * 64;            // 2 warps in M, 64 rows each
    const int n0 = (warp & 1) * 64;             // 2 warps in N, 64 cols each
    const int t4 = lane & 3;
    const int laneA_r  = lane & 15;
    const int laneA_kc = (lane >> 4) & 1;
    const int laneB_r  = (lane & 7) | ((lane >> 4) << 3);
    const int laneB_kc = (lane >> 3) & 1;

    float acc[4][8][4];
    #pragma unroll
    for (int i = 0; i < 4; i++)
        #pragma unroll
        for (int j = 0; j < 8; j++)
            #pragma unroll
            for (int c = 0; c < 4; c++) acc[i][j][c] = 0.0f;

    int st = 0, ph = 0;       // consumer stage/phase
    int pst = 0, pph = 0;     // producer stage/phase

    for (int it = 0; it < KTILES; it++) {
        const uint32_t full  = mbar0 + st * 16;
        const uint32_t empty = full + 8;
        const uint32_t a_s = sb + SMEM_HDR + st * STAGE_BYTES;
        const uint32_t b_s = a_s + A_TILE_BYTES;

        mbar_wait(full, (uint32_t)ph);

        // ks = 0..2
        #pragma unroll
        for (int ks = 0; ks < 3; ks++) {
            uint32_t a[4][4];
            #pragma unroll
            for (int mi = 0; mi < 4; mi++) {
                uint32_t byte = (uint32_t)((m0 + mi * 16 + laneA_r) * 128
                                           + ks * 32 + laneA_kc * 16);
                ldsm_x4(a[mi], a_s + swz128(byte));
            }
            uint32_t b[8][2];
            #pragma unroll
            for (int bi = 0; bi < 4; bi++) {
                uint32_t r[4];
                uint32_t byte = (uint32_t)((n0 + bi * 16 + laneB_r) * 128
                                           + ks * 32 + laneB_kc * 16);
                ldsm_x4(r, b_s + swz128(byte));
                b[2 * bi][0] = r[0]; b[2 * bi][1] = r[1];
                b[2 * bi + 1][0] = r[2]; b[2 * bi + 1][1] = r[3];
            }
            #pragma unroll
            for (int mi = 0; mi < 4; mi++)
                #pragma unroll
                for (int ni = 0; ni < 8; ni++)
                    mma_16816(acc[mi][ni], a[mi], b[ni][0], b[ni][1]);
        }

        // ks = 3, peeled: free the stage right after the final ldmatrix
        {
            const int ks = 3;
            uint32_t a[4][4];
            #pragma unroll
            for (int mi = 0; mi < 4; mi++) {
                uint32_t byte = (uint32_t)((m0 + mi * 16 + laneA_r) * 128
                                           + ks * 32 + laneA_kc * 16);
                ldsm_x4(a[mi], a_s + swz128(byte));
            }
            uint32_t b[8][2];
            #pragma unroll
            for (int bi = 0; bi < 4; bi++) {
                uint32_t r[4];
                uint32_t byte = (uint32_t)((n0 + bi * 16 + laneB_r) * 128
                                           + ks * 32 + laneB_kc * 16);
                ldsm_x4(r, b_s + swz128(byte));
                b[2 * bi][0] = r[0]; b[2 * bi][1] = r[1];
                b[2 * bi + 1][0] = r[2]; b[2 * bi + 1][1] = r[3];
            }
            if (lane == 0) mbar_arrive(empty);
            #pragma unroll
            for (int mi = 0; mi < 4; mi++)
                #pragma unroll
                for (int ni = 0; ni < 8; ni++)
                    mma_16816(acc[mi][ni], a[mi], b[ni][0], b[ni][1]);
        }

        if (tid == 0) {
            const int pre = it + STAGES;
            if (pre < KTILES) {
                const uint32_t pfull = mbar0 + pst * 16;
                const uint32_t pst_s = sb + SMEM_HDR + pst * STAGE_BYTES;
                mbar_wait(pfull + 8, (uint32_t)pph);
                mbar_expect_tx(pfull, STAGE_BYTES);
                bulk_g2s(pst_s, (const char*)g_xh + a_base + (size_t)pre * A_TILE_BYTES,
                         A_TILE_BYTES, pfull);
                bulk_g2s(pst_s + A_TILE_BYTES,
                         (const char*)g_wf + b_base + (size_t)pre * B_TILE_BYTES,
                         B_TILE_BYTES, pfull);
                if (++pst == STAGES) { pst = 0; pph ^= 1; }
            }
        }

        if (++st == STAGES) { st = 0; ph ^= 1; }
    }

    // epilogue: bias + store
    const int g4 = lane >> 2;
    #pragma unroll
    for (int mi = 0; mi < 4; mi++) {
        const int row0 = bm + m0 + mi * 16 + g4;
        #pragma unroll
        for (int ni = 0; ni < 8; ni++) {
            const int col = bn + n0 + ni * 8 + t4 * 2;
            const float2 bz = *reinterpret_cast<const float2*>(&bias[col]);
            float2 v0, v1;
            v0.x = acc[mi][ni][0] + bz.x;
            v0.y = acc[mi][ni][1] + bz.y;
            v1.x = acc[mi][ni][2] + bz.x;
            v1.y = acc[mi][ni][3] + bz.y;
            *reinterpret_cast<float2*>(&out[(size_t)row0 * NDIM + col]) = v0;
            *reinterpret_cast<float2*>(&out[(size_t)(row0 + 8) * NDIM + col]) = v1;
        }
    }
}

// ---------------------------------------------------------------------------
extern "C" void kernel_launch(void* const* d_in, const int* in_sizes, int n_in,
                              void* d_out, int out_size)
{
    const float* x    = (const float*)d_in[0];
    const int*   qw   = (const int*)  d_in[1];
    const int*   qz   = (const int*)  d_in[2];
    const float* sc   = (const float*)d_in[3];
    const float* bias = (const float*)d_in[4];
    float*       out  = (float*)d_out;

    prep<<<XBLKS + WBLKS, 256>>>(x, qw, qz, sc);

    cudaFuncSetAttribute(gemm_mma, cudaFuncAttributeMaxDynamicSharedMemorySize, SMEM_TOTAL);
    dim3 grid(NDIM / BN, MMAX / BM);    // (32, 64)
    gemm_mma<<<grid, NTHREADS, SMEM_TOTAL>>>(bias, out);
}

// round 15
// speedup vs baseline: 1.0134x; 1.0134x over previous
#include <cuda_runtime.h>
#include <cuda_fp16.h>
#include <cstdint>

// GPTQ 4-bit linear, v15: v13 (8 warps, 64x64 warp tile, best 614us) made
// PERSISTENT: grid = #SMs, each CTA walks tiles with one continuous k-pipeline
// (global iteration counter), so TMA stages stay warm across tile boundaries
// and the per-tile fill/drain + epilogue no longer expose an idle tensor pipe.

#define KDIM 4096
#define NDIM 4096
#define MMAX 8192
#define BM 256
#define BN 128
#define BK 64
#define STAGES 4
#define NTHREADS 256
#define KTILES (KDIM / BK)              // 64
#define TILES_X (NDIM / BN)             // 32
#define TILES_Y (MMAX / BM)             // 32
#define NTILES_TOTAL (TILES_X * TILES_Y)  // 1024
#define A_TILE_BYTES (BM * BK * 2)      // 32768
#define B_TILE_BYTES (BN * BK * 2)      // 16384
#define STAGE_BYTES (A_TILE_BYTES + B_TILE_BYTES)     // 49152
#define SMEM_HDR 1024
#define SMEM_TOTAL (SMEM_HDR + STAGES * STAGE_BYTES)  // 197632

#define XBLKS 16384
#define WBLKS 8192

__device__ __align__(1024) __half g_xh[(size_t)MMAX * KDIM];
__device__ __align__(1024) __half g_wf[(size_t)NDIM * KDIM];

__device__ __forceinline__ uint32_t swz128(uint32_t off) {
    return off ^ ((off >> 3) & 0x70);
}
__device__ __forceinline__ uint32_t smem_u32(const void* p) {
    uint32_t a;
    asm("{ .reg .u64 t; cvta.to.shared.u64 t, %1; cvt.u32.u64 %0, t; }" : "=r"(a) : "l"(p));
    return a;
}
__device__ __forceinline__ void mbar_init(uint32_t mbar, uint32_t count) {
    asm volatile("mbarrier.init.shared.b64 [%0], %1;" :: "r"(mbar), "r"(count) : "memory");
}
__device__ __forceinline__ void mbar_expect_tx(uint32_t mbar, uint32_t bytes) {
    asm volatile("mbarrier.arrive.expect_tx.shared.b64 _, [%0], %1;" :: "r"(mbar), "r"(bytes) : "memory");
}
__device__ __forceinline__ void mbar_arrive(uint32_t mbar) {
    asm volatile("mbarrier.arrive.shared.b64 _, [%0];" :: "r"(mbar) : "memory");
}
__device__ __forceinline__ void mbar_wait(uint32_t mbar, uint32_t parity) {
    asm volatile(
        "{\n\t.reg .pred P;\n\t"
        "WAIT_%=:\n\t"
        "mbarrier.try_wait.parity.acquire.cta.shared::cta.b64 P, [%0], %1, 0x989680;\n\t"
        "@!P bra WAIT_%=;\n\t}"
        :: "r"(mbar), "r"(parity) : "memory");
}
__device__ __forceinline__ void bulk_g2s(uint32_t dst, const void* src, uint32_t bytes, uint32_t mbar) {
    asm volatile(
        "cp.async.bulk.shared::cluster.global.mbarrier::complete_tx::bytes [%0], [%1], %2, [%3];"
        :: "r"(dst), "l"(src), "r"(bytes), "r"(mbar) : "memory");
}
__device__ __forceinline__ void ldsm_x4(uint32_t* r, uint32_t addr) {
    asm volatile("ldmatrix.sync.aligned.m8n8.x4.shared.b16 {%0,%1,%2,%3}, [%4];"
                 : "=r"(r[0]), "=r"(r[1]), "=r"(r[2]), "=r"(r[3]) : "r"(addr));
}
__device__ __forceinline__ void mma_16816(float* c, const uint32_t* a, uint32_t b0, uint32_t b1) {
    asm volatile(
        "mma.sync.aligned.m16n8k16.row.col.f32.f16.f16.f32 "
        "{%0,%1,%2,%3}, {%4,%5,%6,%7}, {%8,%9}, {%0,%1,%2,%3};"
        : "+f"(c[0]), "+f"(c[1]), "+f"(c[2]), "+f"(c[3])
        : "r"(a[0]), "r"(a[1]), "r"(a[2]), "r"(a[3]), "r"(b0), "r"(b1));
}

// ---------------------------------------------------------------------------
// Fused prep: blocks [0, XBLKS) convert x; blocks [XBLKS, XBLKS+WBLKS) build W.
// ---------------------------------------------------------------------------
__global__ void prep(const float* __restrict__ x,
                     const int* __restrict__ qw, const int* __restrict__ qz,
                     const float* __restrict__ sc) {
    if (blockIdx.x < XBLKS) {
        size_t idx = (size_t)blockIdx.x * blockDim.x + threadIdx.x;  // per 8 elems
        int m  = (int)(idx >> 9);
        int k0 = ((int)idx & 511) << 3;

        const float* src = x + (size_t)m * KDIM + k0;
        float4 v0 = *reinterpret_cast<const float4*>(src);
        float4 v1 = *reinterpret_cast<const float4*>(src + 4);

        union { __half h[8]; uint4 u; } d;
        d.h[0] = __float2half_rn(v0.x); d.h[1] = __float2half_rn(v0.y);
        d.h[2] = __float2half_rn(v0.z); d.h[3] = __float2half_rn(v0.w);
        d.h[4] = __float2half_rn(v1.x); d.h[5] = __float2half_rn(v1.y);
        d.h[6] = __float2half_rn(v1.z); d.h[7] = __float2half_rn(v1.w);

        size_t off = ((size_t)(m >> 8) * KTILES + (k0 >> 6)) * A_TILE_BYTES
                   + swz128((uint32_t)((m & 255) * 128 + (k0 & 63) * 2));
        *reinterpret_cast<uint4*>(reinterpret_cast<char*>(g_xh) + off) = d.u;
    } else {
        int idx = (blockIdx.x - XBLKS) * blockDim.x + threadIdx.x;  // per qw word
        int kw = idx >> 12;                 // k/8: 0..511
        int n  = idx & 4095;
        int g  = kw >> 4;                   // k/128
        float s = sc[g * NDIM + n];
        int z = ((qz[g * (NDIM / 8) + (n >> 3)] >> ((n & 7) * 4)) & 15) + 1;
        int w = qw[kw * NDIM + n];

        union { __half h[8]; uint4 u; } d;
        #pragma unroll
        for (int j = 0; j < 8; j++) {
            int q = (w >> (j * 4)) & 15;
            d.h[j] = __float2half_rn(s * (float)(q - z));
        }

        int k0 = kw << 3;
        size_t off = ((size_t)(n >> 7) * KTILES + (k0 >> 6)) * B_TILE_BYTES
                   + swz128((uint32_t)((n & 127) * 128 + (k0 & 63) * 2));
        *reinterpret_cast<uint4*>(reinterpret_cast<char*>(g_wf) + off) = d.u;
    }
}

// tile index helpers: flat tile t -> scratch bases
__device__ __forceinline__ size_t a_base_of(int t) {
    return (size_t)(t >> 5) * (KTILES * A_TILE_BYTES);
}
__device__ __forceinline__ size_t b_base_of(int t) {
    return (size_t)(t & 31) * (KTILES * B_TILE_BYTES);
}

// ---------------------------------------------------------------------------
// GEMM: persistent, 8 warps, warp tile 64x64, tid0 producer, continuous pipeline
// ---------------------------------------------------------------------------
__global__ __launch_bounds__(NTHREADS, 1)
void gemm_mma(const float* __restrict__ bias, float* __restrict__ out) {
    extern __shared__ char smem[];
    const uint32_t sb = smem_u32(smem);
    const int tid = threadIdx.x;
    const int bid = blockIdx.x;
    const int gsz = gridDim.x;

    const uint32_t mbar0 = sb;   // full[s]=sb+s*16, empty[s]=sb+s*16+8

    if (tid == 0) {
        #pragma unroll
        for (int s = 0; s < STAGES; s++) {
            mbar_init(mbar0 + s * 16, 1);       // full: tx-based
            mbar_init(mbar0 + s * 16 + 8, 8);   // empty: one arrive per warp
        }
    }
    __syncthreads();

    if (bid >= NTILES_TOTAL) return;
    const int ntiles = (NTILES_TOTAL - 1 - bid) / gsz + 1;   // this CTA's tile count
    const int G = ntiles << 6;                               // total k-iterations

    if (tid == 0) {
        const size_t a0 = a_base_of(bid);
        const size_t b0 = b_base_of(bid);
        #pragma unroll
        for (int s = 0; s < STAGES; s++) {      // prologue: tile 0, k-tiles 0..3
            uint32_t full = mbar0 + s * 16;
            uint32_t st_s = sb + SMEM_HDR + s * STAGE_BYTES;
            mbar_expect_tx(full, STAGE_BYTES);
            bulk_g2s(st_s, (const char*)g_xh + a0 + (size_t)s * A_TILE_BYTES,
                     A_TILE_BYTES, full);
            bulk_g2s(st_s + A_TILE_BYTES,
                     (const char*)g_wf + b0 + (size_t)s * B_TILE_BYTES,
                     B_TILE_BYTES, full);
        }
    }

    const int warp = tid >> 5, lane = tid & 31;
    const int m0 = (warp >> 1) * 64;            // 4 warps in M, 64 rows each
    const int n0 = (warp & 1) * 64;             // 2 warps in N, 64 cols each
    const int t4 = lane & 3;
    const int laneA_r  = lane & 15;
    const int laneA_kc = (lane >> 4) & 1;
    const int laneB_r  = (lane & 7) | ((lane >> 4) << 3);
    const int laneB_kc = (lane >> 3) & 1;
    const int g4 = lane >> 2;

    float acc[4][8][4];
    #pragma unroll
    for (int i = 0; i < 4; i++)
        #pragma unroll
        for (int j = 0; j < 8; j++)
            #pragma unroll
            for (int c = 0; c < 4; c++) acc[i][j][c] = 0.0f;

    for (int g = 0; g < G; g++) {
        const int st = g & (STAGES - 1);
        const uint32_t ph = (uint32_t)(g >> 2) & 1u;
        const uint32_t full  = mbar0 + st * 16;
        const uint32_t empty = full + 8;
        const uint32_t a_s = sb + SMEM_HDR + st * STAGE_BYTES;
        const uint32_t b_s = a_s + A_TILE_BYTES;

        mbar_wait(full, ph);

        // ks = 0..2
        #pragma unroll
        for (int ks = 0; ks < 3; ks++) {
            uint32_t a[4][4];
            #pragma unroll
            for (int mi = 0; mi < 4; mi++) {
                uint32_t byte = (uint32_t)((m0 + mi * 16 + laneA_r) * 128
                                           + ks * 32 + laneA_kc * 16);
                ldsm_x4(a[mi], a_s + swz128(byte));
            }
            uint32_t b[8][2];
            #pragma unroll
            for (int bi = 0; bi < 4; bi++) {
                uint32_t r[4];
                uint32_t byte = (uint32_t)((n0 + bi * 16 + laneB_r) * 128
                                           + ks * 32 + laneB_kc * 16);
                ldsm_x4(r, b_s + swz128(byte));
                b[2 * bi][0] = r[0]; b[2 * bi][1] = r[1];
                b[2 * bi + 1][0] = r[2]; b[2 * bi + 1][1] = r[3];
            }
            #pragma unroll
            for (int mi = 0; mi < 4; mi++)
                #pragma unroll
                for (int ni = 0; ni < 8; ni++)
                    mma_16816(acc[mi][ni], a[mi], b[ni][0], b[ni][1]);
        }

        // ks = 3, peeled: free the stage right after the final ldmatrix
        {
            const int ks = 3;
            uint32_t a[4][4];
            #pragma unroll
            for (int mi = 0; mi < 4; mi++) {
                uint32_t byte = (uint32_t)((m0 + mi * 16 + laneA_r) * 128
                                           + ks * 32 + laneA_kc * 16);
                ldsm_x4(a[mi], a_s + swz128(byte));
            }
            uint32_t b[8][2];
            #pragma unroll
            for (int bi = 0; bi < 4; bi++) {
                uint32_t r[4];
                uint32_t byte = (uint32_t)((n0 + bi * 16 + laneB_r) * 128
                                           + ks * 32 + laneB_kc * 16);
                ldsm_x4(r, b_s + swz128(byte));
                b[2 * bi][0] = r[0]; b[2 * bi][1] = r[1];
                b[2 * bi + 1][0] = r[2]; b[2 * bi + 1][1] = r[3];
            }
            if (lane == 0) mbar_arrive(empty);
            #pragma unroll
            for (int mi = 0; mi < 4; mi++)
                #pragma unroll
                for (int ni = 0; ni < 8; ni++)
                    mma_16816(acc[mi][ni], a[mi], b[ni][0], b[ni][1]);
        }

        // producer: refill stage st for global iteration g+STAGES (may cross tiles)
        if (tid == 0) {
            const int pre = g + STAGES;
            if (pre < G) {
                const int pt = bid + (pre >> 6) * gsz;     // future tile id
                const int pit = pre & 63;                  // its k-tile
                mbar_wait(empty, ph);
                mbar_expect_tx(full, STAGE_BYTES);
                bulk_g2s(a_s, (const char*)g_xh + a_base_of(pt)
                              + (size_t)pit * A_TILE_BYTES, A_TILE_BYTES, full);
                bulk_g2s(b_s, (const char*)g_wf + b_base_of(pt)
                              + (size_t)pit * B_TILE_BYTES, B_TILE_BYTES, full);
            }
        }

        // tile boundary: epilogue + accumulator reset (pipeline keeps running)
        if ((g & 63) == 63) {
            const int t = bid + (g >> 6) * gsz;
            const int bm = (t >> 5) * BM;
            const int bn = (t & 31) * BN;
            #pragma unroll
            for (int mi = 0; mi < 4; mi++) {
                const int row0 = bm + m0 + mi * 16 + g4;
                #pragma unroll
                for (int ni = 0; ni < 8; ni++) {
                    const int col = bn + n0 + ni * 8 + t4 * 2;
                    const float2 bz = *reinterpret_cast<const float2*>(&bias[col]);
                    float2 v0, v1;
                    v0.x = acc[mi][ni][0] + bz.x;
                    v0.y = acc[mi][ni][1] + bz.y;
                    v1.x = acc[mi][ni][2] + bz.x;
                    v1.y = acc[mi][ni][3] + bz.y;
                    *reinterpret_cast<float2*>(&out[(size_t)row0 * NDIM + col]) = v0;
                    *reinterpret_cast<float2*>(&out[(size_t)(row0 + 8) * NDIM + col]) = v1;
                    acc[mi][ni][0] = 0.0f; acc[mi][ni][1] = 0.0f;
                    acc[mi][ni][2] = 0.0f; acc[mi][ni][3] = 0.0f;
                }
            }
        }
    }
}

// ---------------------------------------------------------------------------
extern "C" void kernel_launch(void* const* d_in, const int* in_sizes, int n_in,
                              void* d_out, int out_size)
{
    const float* x    = (const float*)d_in[0];
    const int*   qw   = (const int*)  d_in[1];
    const int*   qz   = (const int*)  d_in[2];
    const float* sc   = (const float*)d_in[3];
    const float* bias = (const float*)d_in[4];
    float*       out  = (float*)d_out;

    prep<<<XBLKS + WBLKS, 256>>>(x, qw, qz, sc);

    int nsm = 148;
    cudaDeviceGetAttribute(&nsm, cudaDevAttrMultiProcessorCount, 0);
    if (nsm <= 0 || nsm > NTILES_TOTAL) nsm = 148;

    cudaFuncSetAttribute(gemm_mma, cudaFuncAttributeMaxDynamicSharedMemorySize, SMEM_TOTAL);
    gemm_mma<<<nsm, NTHREADS, SMEM_TOTAL>>>(bias, out);
}